// round 7
// baseline (speedup 1.0000x reference)
#include <cuda_runtime.h>
#include <cstddef>

// RNN_22883585753135: 2-layer tanh RNN, B=64, T=4096, IN=H=128
//   out = concat( out1[B,T,H], h_n[2,B,H] )
//
// Round 7: decoupled proj/rec, NO inter-CTA sync (de-risked after two
// container failures on the pipelined variant).
//   rnn_layer kernel, launched twice (layer 0 then layer 1):
//     64 CTAs (one per batch row) x 256 threads.
//     proj group (thr 128..255): chunk-granular free-running GEMM
//         z[t] = Wih * v[t] + (bih+bhh) into ping-pong zbuf; internal
//         bar.sync 2,128 only.
//     rec group (thr 0..127): per-step h[t] = tanh(z[t] + Whh h[t-1]),
//         bar.sync 1,128 per step (proj never blocks it).
//     Groups meet once per CHUNK at __syncthreads.

typedef unsigned long long ull;

#define BB 64
#define TT 4096
#define HH 128
#define BT (BB * TT)
#define CHUNK 16
#define NCHUNK (TT / CHUNK)

// Scratch (allocation-free rule): layer-0 output
__device__ __align__(16) float g_h0[(size_t)BT * HH];

// ---------------- packed f32x2 helpers (sm_100+) ----------------
__device__ __forceinline__ ull fma2(ull a, ull b, ull c) {
    ull d;
    asm("fma.rn.f32x2 %0, %1, %2, %3;" : "=l"(d) : "l"(a), "l"(b), "l"(c));
    return d;
}
__device__ __forceinline__ ull add2(ull a, ull b) {
    ull d;
    asm("add.rn.f32x2 %0, %1, %2;" : "=l"(d) : "l"(a), "l"(b));
    return d;
}
__device__ __forceinline__ float2 unpack2(ull v) {
    float2 f;
    asm("mov.b64 {%0, %1}, %2;" : "=f"(f.x), "=f"(f.y) : "l"(v));
    return f;
}

#define BAR_REC()  asm volatile("bar.sync 1, 128;" ::: "memory")
#define BAR_PROJ() asm volatile("bar.sync 2, 128;" ::: "memory")

// tanh(x) = 1 - 2/(e^{2x}+1); branch-free, exact limits, ~1e-7 rel
__device__ __forceinline__ float tanh_acc(float x) {
    float e = __expf(2.0f * x);
    return 1.0f - __fdividef(2.0f, e + 1.0f);
}

// 128-wide dot: register row (64 packed f32x2) x 16B-aligned smem vector.
// 8 accumulator chains -> dependent FFMA2 depth 8.
__device__ __forceinline__ float dot128_8(const ull* w, const float* hbuf) {
    const ulonglong2* hv = (const ulonglong2*)hbuf;
    ull a0=0ull,a1=0ull,a2=0ull,a3=0ull,a4=0ull,a5=0ull,a6=0ull,a7=0ull;
    #pragma unroll
    for (int k = 0; k < 32; k += 4) {
        ulonglong2 h01 = hv[k];
        ulonglong2 h23 = hv[k + 1];
        ulonglong2 h45 = hv[k + 2];
        ulonglong2 h67 = hv[k + 3];
        a0 = fma2(h01.x, w[2*k+0], a0);
        a1 = fma2(h01.y, w[2*k+1], a1);
        a2 = fma2(h23.x, w[2*k+2], a2);
        a3 = fma2(h23.y, w[2*k+3], a3);
        a4 = fma2(h45.x, w[2*k+4], a4);
        a5 = fma2(h45.y, w[2*k+5], a5);
        a6 = fma2(h67.x, w[2*k+6], a6);
        a7 = fma2(h67.y, w[2*k+7], a7);
    }
    ull s0 = add2(a0, a4), s1 = add2(a1, a5);
    ull s2 = add2(a2, a6), s3 = add2(a3, a7);
    float2 v = unpack2(add2(add2(s0, s2), add2(s1, s3)));
    return v.x + v.y;
}

// ---------------- one RNN layer, decoupled proj/rec ----------------
__global__ void __launch_bounds__(256, 1) rnn_layer(
    const float* __restrict__ vsrc,   // [B,T,HH] layer input
    const float* __restrict__ Wih, const float* __restrict__ Whh,
    const float* __restrict__ bih, const float* __restrict__ bhh,
    float* __restrict__ hout,         // [B,T,HH] layer output
    float* __restrict__ hNout)        // [B,HH]   final hidden state
{
    const int b   = blockIdx.x;
    const int tid = threadIdx.x;
    const int grp = tid >> 7;          // 0 = rec, 1 = proj
    const int j   = tid & 127;

    __shared__ __align__(16) float vbuf[CHUNK][HH];      // staged inputs
    __shared__ __align__(16) float zbuf[2][CHUNK][HH];   // z ping-pong
    __shared__ __align__(16) float hs[2][HH];            // recurrent state

    // weight row -> 64 packed f32x2 registers
    ull w[64];
    {
        const float* wsrc = (grp == 1 ? Wih : Whh) + (size_t)j * HH;
        const ull* wg = (const ull*)wsrc;
        #pragma unroll
        for (int i = 0; i < 64; i++) w[i] = wg[i];
    }

    float bias = 0.0f;
    if (grp == 1) bias = __ldg(bih + j) + __ldg(bhh + j);

    const float* vp = vsrc + (size_t)b * TT * HH;
    float*       hp = hout + (size_t)b * TT * HH;

    if (grp == 0) { hs[0][j] = 0.0f; hs[1][j] = 0.0f; }

    // ---- prologue: proj computes chunk 0 into zbuf[0] ----
    if (grp == 1) {
        #pragma unroll
        for (int i = 0; i < CHUNK; i++)
            vbuf[i][j] = __ldg(vp + (size_t)i * HH + j);
        BAR_PROJ();
        #pragma unroll 2
        for (int t = 0; t < CHUNK; t++)
            zbuf[0][t][j] = dot128_8(w, vbuf[t]) + bias;
    }
    __syncthreads();

    // ---- main loop over chunks ----
    for (int c = 0; c < NCHUNK; c++) {
        if (grp == 1) {
            if (c + 1 < NCHUNK) {
                const size_t row0 = (size_t)(c + 1) * CHUNK;
                BAR_PROJ();                           // prior dots done reading vbuf
                #pragma unroll
                for (int i = 0; i < CHUNK; i++)
                    vbuf[i][j] = __ldg(vp + (row0 + i) * HH + j);
                BAR_PROJ();                           // vbuf staged
                const int zp = (c + 1) & 1;
                #pragma unroll 2
                for (int t = 0; t < CHUNK; t++)
                    zbuf[zp][t][j] = dot128_8(w, vbuf[t]) + bias;
            }
        } else {
            const int zp = c & 1;
            const size_t s0 = (size_t)c * CHUNK;
            #pragma unroll 2
            for (int t = 0; t < CHUNK; t++) {
                const int p = t & 1;                  // CHUNK even -> global parity
                float hn = tanh_acc(dot128_8(w, hs[p]) + zbuf[zp][t][j]);
                hs[p ^ 1][j] = hn;
                hp[(s0 + t) * HH + j] = hn;
                BAR_REC();
            }
        }
        __syncthreads();                              // chunk handoff
    }

    // last step (t=15, p=1) wrote hs[0] = h[T-1]
    if (grp == 0) hNout[(size_t)b * HH + j] = hs[0][j];
}

// ---------------- launch ----------------
extern "C" void kernel_launch(void* const* d_in, const int* in_sizes, int n_in,
                              void* d_out, int out_size)
{
    const float* x     = (const float*)d_in[0];
    const float* W_ih0 = (const float*)d_in[1];
    const float* W_hh0 = (const float*)d_in[2];
    const float* b_ih0 = (const float*)d_in[3];
    const float* b_hh0 = (const float*)d_in[4];
    const float* W_ih1 = (const float*)d_in[5];
    const float* W_hh1 = (const float*)d_in[6];
    const float* b_ih1 = (const float*)d_in[7];
    const float* b_hh1 = (const float*)d_in[8];

    float* out1 = (float*)d_out;                 // [B,T,H]
    float* hN   = out1 + (size_t)BT * HH;        // [2,B,H]

    void* h0_p = nullptr;
    cudaGetSymbolAddress(&h0_p, g_h0);
    float* h0 = (float*)h0_p;

    // layer 0: x -> g_h0, hN[0]
    rnn_layer<<<BB, 256>>>(x,  W_ih0, W_hh0, b_ih0, b_hh0, h0,   hN);
    // layer 1: g_h0 -> out1, hN[1]
    rnn_layer<<<BB, 256>>>(h0, W_ih1, W_hh1, b_ih1, b_hh1, out1, hN + BB * HH);
}

// round 8
// speedup vs baseline: 1.0000x; 1.0000x over previous
#include <cuda_runtime.h>
#include <cstddef>

// RNN_22883585753135: 2-layer tanh RNN, B=64, T=4096, IN=H=128
//   out = concat( out1[B,T,H], h_n[2,B,H] )
//
// Round 7: decoupled proj/rec, NO inter-CTA sync (de-risked after two
// container failures on the pipelined variant).
//   rnn_layer kernel, launched twice (layer 0 then layer 1):
//     64 CTAs (one per batch row) x 256 threads.
//     proj group (thr 128..255): chunk-granular free-running GEMM
//         z[t] = Wih * v[t] + (bih+bhh) into ping-pong zbuf; internal
//         bar.sync 2,128 only.
//     rec group (thr 0..127): per-step h[t] = tanh(z[t] + Whh h[t-1]),
//         bar.sync 1,128 per step (proj never blocks it).
//     Groups meet once per CHUNK at __syncthreads.

typedef unsigned long long ull;

#define BB 64
#define TT 4096
#define HH 128
#define BT (BB * TT)
#define CHUNK 16
#define NCHUNK (TT / CHUNK)

// Scratch (allocation-free rule): layer-0 output
__device__ __align__(16) float g_h0[(size_t)BT * HH];

// ---------------- packed f32x2 helpers (sm_100+) ----------------
__device__ __forceinline__ ull fma2(ull a, ull b, ull c) {
    ull d;
    asm("fma.rn.f32x2 %0, %1, %2, %3;" : "=l"(d) : "l"(a), "l"(b), "l"(c));
    return d;
}
__device__ __forceinline__ ull add2(ull a, ull b) {
    ull d;
    asm("add.rn.f32x2 %0, %1, %2;" : "=l"(d) : "l"(a), "l"(b));
    return d;
}
__device__ __forceinline__ float2 unpack2(ull v) {
    float2 f;
    asm("mov.b64 {%0, %1}, %2;" : "=f"(f.x), "=f"(f.y) : "l"(v));
    return f;
}

#define BAR_REC()  asm volatile("bar.sync 1, 128;" ::: "memory")
#define BAR_PROJ() asm volatile("bar.sync 2, 128;" ::: "memory")

// tanh(x) = 1 - 2/(e^{2x}+1); branch-free, exact limits, ~1e-7 rel
__device__ __forceinline__ float tanh_acc(float x) {
    float e = __expf(2.0f * x);
    return 1.0f - __fdividef(2.0f, e + 1.0f);
}

// 128-wide dot: register row (64 packed f32x2) x 16B-aligned smem vector.
// 8 accumulator chains -> dependent FFMA2 depth 8.
__device__ __forceinline__ float dot128_8(const ull* w, const float* hbuf) {
    const ulonglong2* hv = (const ulonglong2*)hbuf;
    ull a0=0ull,a1=0ull,a2=0ull,a3=0ull,a4=0ull,a5=0ull,a6=0ull,a7=0ull;
    #pragma unroll
    for (int k = 0; k < 32; k += 4) {
        ulonglong2 h01 = hv[k];
        ulonglong2 h23 = hv[k + 1];
        ulonglong2 h45 = hv[k + 2];
        ulonglong2 h67 = hv[k + 3];
        a0 = fma2(h01.x, w[2*k+0], a0);
        a1 = fma2(h01.y, w[2*k+1], a1);
        a2 = fma2(h23.x, w[2*k+2], a2);
        a3 = fma2(h23.y, w[2*k+3], a3);
        a4 = fma2(h45.x, w[2*k+4], a4);
        a5 = fma2(h45.y, w[2*k+5], a5);
        a6 = fma2(h67.x, w[2*k+6], a6);
        a7 = fma2(h67.y, w[2*k+7], a7);
    }
    ull s0 = add2(a0, a4), s1 = add2(a1, a5);
    ull s2 = add2(a2, a6), s3 = add2(a3, a7);
    float2 v = unpack2(add2(add2(s0, s2), add2(s1, s3)));
    return v.x + v.y;
}

// ---------------- one RNN layer, decoupled proj/rec ----------------
__global__ void __launch_bounds__(256, 1) rnn_layer(
    const float* __restrict__ vsrc,   // [B,T,HH] layer input
    const float* __restrict__ Wih, const float* __restrict__ Whh,
    const float* __restrict__ bih, const float* __restrict__ bhh,
    float* __restrict__ hout,         // [B,T,HH] layer output
    float* __restrict__ hNout)        // [B,HH]   final hidden state
{
    const int b   = blockIdx.x;
    const int tid = threadIdx.x;
    const int grp = tid >> 7;          // 0 = rec, 1 = proj
    const int j   = tid & 127;

    __shared__ __align__(16) float vbuf[CHUNK][HH];      // staged inputs
    __shared__ __align__(16) float zbuf[2][CHUNK][HH];   // z ping-pong
    __shared__ __align__(16) float hs[2][HH];            // recurrent state

    // weight row -> 64 packed f32x2 registers
    ull w[64];
    {
        const float* wsrc = (grp == 1 ? Wih : Whh) + (size_t)j * HH;
        const ull* wg = (const ull*)wsrc;
        #pragma unroll
        for (int i = 0; i < 64; i++) w[i] = wg[i];
    }

    float bias = 0.0f;
    if (grp == 1) bias = __ldg(bih + j) + __ldg(bhh + j);

    const float* vp = vsrc + (size_t)b * TT * HH;
    float*       hp = hout + (size_t)b * TT * HH;

    if (grp == 0) { hs[0][j] = 0.0f; hs[1][j] = 0.0f; }

    // ---- prologue: proj computes chunk 0 into zbuf[0] ----
    if (grp == 1) {
        #pragma unroll
        for (int i = 0; i < CHUNK; i++)
            vbuf[i][j] = __ldg(vp + (size_t)i * HH + j);
        BAR_PROJ();
        #pragma unroll 2
        for (int t = 0; t < CHUNK; t++)
            zbuf[0][t][j] = dot128_8(w, vbuf[t]) + bias;
    }
    __syncthreads();

    // ---- main loop over chunks ----
    for (int c = 0; c < NCHUNK; c++) {
        if (grp == 1) {
            if (c + 1 < NCHUNK) {
                const size_t row0 = (size_t)(c + 1) * CHUNK;
                BAR_PROJ();                           // prior dots done reading vbuf
                #pragma unroll
                for (int i = 0; i < CHUNK; i++)
                    vbuf[i][j] = __ldg(vp + (row0 + i) * HH + j);
                BAR_PROJ();                           // vbuf staged
                const int zp = (c + 1) & 1;
                #pragma unroll 2
                for (int t = 0; t < CHUNK; t++)
                    zbuf[zp][t][j] = dot128_8(w, vbuf[t]) + bias;
            }
        } else {
            const int zp = c & 1;
            const size_t s0 = (size_t)c * CHUNK;
            #pragma unroll 2
            for (int t = 0; t < CHUNK; t++) {
                const int p = t & 1;                  // CHUNK even -> global parity
                float hn = tanh_acc(dot128_8(w, hs[p]) + zbuf[zp][t][j]);
                hs[p ^ 1][j] = hn;
                hp[(s0 + t) * HH + j] = hn;
                BAR_REC();
            }
        }
        __syncthreads();                              // chunk handoff
    }

    // last step (t=15, p=1) wrote hs[0] = h[T-1]
    if (grp == 0) hNout[(size_t)b * HH + j] = hs[0][j];
}

// ---------------- launch ----------------
extern "C" void kernel_launch(void* const* d_in, const int* in_sizes, int n_in,
                              void* d_out, int out_size)
{
    const float* x     = (const float*)d_in[0];
    const float* W_ih0 = (const float*)d_in[1];
    const float* W_hh0 = (const float*)d_in[2];
    const float* b_ih0 = (const float*)d_in[3];
    const float* b_hh0 = (const float*)d_in[4];
    const float* W_ih1 = (const float*)d_in[5];
    const float* W_hh1 = (const float*)d_in[6];
    const float* b_ih1 = (const float*)d_in[7];
    const float* b_hh1 = (const float*)d_in[8];

    float* out1 = (float*)d_out;                 // [B,T,H]
    float* hN   = out1 + (size_t)BT * HH;        // [2,B,H]

    void* h0_p = nullptr;
    cudaGetSymbolAddress(&h0_p, g_h0);
    float* h0 = (float*)h0_p;

    // layer 0: x -> g_h0, hN[0]
    rnn_layer<<<BB, 256>>>(x,  W_ih0, W_hh0, b_ih0, b_hh0, h0,   hN);
    // layer 1: g_h0 -> out1, hN[1]
    rnn_layer<<<BB, 256>>>(h0, W_ih1, W_hh1, b_ih1, b_hh1, out1, hN + BB * HH);
}